// round 14
// baseline (speedup 1.0000x reference)
#include <cuda_runtime.h>
#include <cuda_bf16.h>
#include <stdint.h>
#include <math.h>

#define Bsz 64
#define Vv  50000
#define Ee  512
#define Hh  1024
#define LQv 32
#define LDv 400

// ---------------- scratch ----------------
__device__ float g_embedded[Bsz * Ee];
__device__ float g_qh[Bsz * Hh];
__device__ float g_scoreq[Bsz * LQv];
__device__ float g_ctxq[Bsz * Hh];
__device__ float g_dq[Bsz * 2 * Hh];
__device__ float g_dqh[Bsz * Hh];
__device__ float g_ehd[(size_t)LDv * Bsz * Hh];   // ~105 MB
__device__ float g_ctxd[Bsz * Hh];
__device__ float g_gates[Bsz * 4 * Hh];
__device__ float g_dgates[Bsz * 4 * Hh];
__device__ float g_rnn[Bsz * (Hh + Ee)];

// ================= HMMA bf16 split-precision GEMM =================
// K-slab 16, smem row stride 24 u16 (48B): ldsm 8-row phases hit distinct banks.
#define SK   16
#define SST  24

__device__ __forceinline__ void mma16816(float* d, const uint32_t* a, const uint32_t* b) {
    asm volatile(
        "mma.sync.aligned.m16n8k16.row.col.f32.bf16.bf16.f32 "
        "{%0,%1,%2,%3}, {%4,%5,%6,%7}, {%8,%9}, {%0,%1,%2,%3};"
        : "+f"(d[0]), "+f"(d[1]), "+f"(d[2]), "+f"(d[3])
        : "r"(a[0]), "r"(a[1]), "r"(a[2]), "r"(a[3]), "r"(b[0]), "r"(b[1]));
}

__device__ __forceinline__ void ldsm4(uint32_t& r0, uint32_t& r1, uint32_t& r2, uint32_t& r3,
                                      uint32_t addr) {
    asm volatile("ldmatrix.sync.aligned.m8n8.x4.shared.b16 {%0,%1,%2,%3}, [%4];"
                 : "=r"(r0), "=r"(r1), "=r"(r2), "=r"(r3) : "r"(addr));
}

__device__ __forceinline__ uint32_t s2u(const void* p) {
    uint32_t a;
    asm("{ .reg .u64 t; cvta.to.shared.u64 t, %1; cvt.u32.u64 %0, t; }" : "=r"(a) : "l"(p));
    return a;
}

__device__ __forceinline__ void cvt_store(uint16_t* hi, uint16_t* lo, int off, float4 v) {
    __nv_bfloat162 h01 = __floats2bfloat162_rn(v.x, v.y);
    __nv_bfloat162 h23 = __floats2bfloat162_rn(v.z, v.w);
    float2 f01 = __bfloat1622float2(h01);
    float2 f23 = __bfloat1622float2(h23);
    __nv_bfloat162 l01 = __floats2bfloat162_rn(v.x - f01.x, v.y - f01.y);
    __nv_bfloat162 l23 = __floats2bfloat162_rn(v.z - f23.x, v.w - f23.y);
    *(uint2*)(hi + off) = make_uint2(*(uint32_t*)&h01, *(uint32_t*)&h23);
    *(uint2*)(lo + off) = make_uint2(*(uint32_t*)&l01, *(uint32_t*)&l23);
}

// WMY=2: block 128x128, 4 warps, warp tile 64x64 (occ 2)
// WMY=1: block  64x128, 4 warps, warp tile 64x32 (occ 3) -- for M<=64 GEMMs
template <int WMY, int OCC>
__global__ __launch_bounds__(128, OCC) void hgemm(
    const float* __restrict__ A, int lda,
    const float* __restrict__ B, int ldb,
    float* __restrict__ C, int ldc,
    int M, int N, int K, int mode,
    const float* __restrict__ qadd, const float* __restrict__ bias,
    const float* __restrict__ vvec, float* __restrict__ score, int T)
{
    const int BM  = WMY * 64;
    const int WN_ = 4 / WMY;          // warps along N
    const int WTN = 128 / WN_;        // warp N-tile (64 or 32)
    const int JT  = WTN / 8;          // 8 or 4 j-tiles
    const int NF4A = BM / 32;         // float4 per thread for A slab

    __shared__ __align__(16) uint16_t As[2][BM * SST];
    __shared__ __align__(16) uint16_t Bs[2][128 * SST];
    uint16_t* Ah = As[0];
    uint16_t* Al = As[1];
    uint16_t* Bh = Bs[0];
    uint16_t* Bl = Bs[1];

    int tid  = threadIdx.x;
    int lane = tid & 31;
    int w    = tid >> 5;              // 0..3
    int g    = lane >> 2;
    int tg   = lane & 3;
    int wm   = w / WN_;
    int wn   = w % WN_;

    int mrow0 = blockIdx.y * BM;
    int nrow0 = blockIdx.x * 128;

    uint32_t aoff = (uint32_t)((wm * 64 + (lane & 15)) * (SST * 2) + ((lane >> 4) & 1) * 16);
    uint32_t boff = (uint32_t)((wn * WTN + ((lane >> 4) & 1) * 8 + (lane & 7)) * (SST * 2)
                               + ((lane >> 3) & 1) * 16);
    uint32_t uAh = s2u(Ah) + aoff, uAl = s2u(Al) + aoff;
    uint32_t uBh = s2u(Bh) + boff, uBl = s2u(Bl) + boff;

    float acc[4][JT][4];
#pragma unroll
    for (int i = 0; i < 4; i++)
#pragma unroll
        for (int j = 0; j < JT; j++)
#pragma unroll
            for (int q = 0; q < 4; q++) acc[i][j][q] = 0.f;

    const float4 Z4 = make_float4(0.f, 0.f, 0.f, 0.f);
    float4 va[NF4A], vb[4];

    // prefetch slab 0: each float4 f covers (row = f>>2, cols (f&3)*4 .. +3)
#pragma unroll
    for (int i = 0; i < NF4A; i++) {
        int f = tid * NF4A + i;
        int row = f >> 2, c4 = (f & 3) << 2;
        int gm = mrow0 + row;
        va[i] = (gm < M) ? *(const float4*)(A + (size_t)gm * lda + c4) : Z4;
    }
#pragma unroll
    for (int i = 0; i < 4; i++) {
        int f = tid * 4 + i;
        int row = f >> 2, c4 = (f & 3) << 2;
        int gn = nrow0 + row;
        vb[i] = (gn < N) ? *(const float4*)(B + (size_t)gn * ldb + c4) : Z4;
    }

    int ns = K / SK;
    for (int s = 0; s < ns; s++) {
#pragma unroll
        for (int i = 0; i < NF4A; i++) {
            int f = tid * NF4A + i;
            cvt_store(Ah, Al, (f >> 2) * SST + ((f & 3) << 2), va[i]);
        }
#pragma unroll
        for (int i = 0; i < 4; i++) {
            int f = tid * 4 + i;
            cvt_store(Bh, Bl, (f >> 2) * SST + ((f & 3) << 2), vb[i]);
        }
        __syncthreads();

        if (s + 1 < ns) {
            int k0 = (s + 1) * SK;
#pragma unroll
            for (int i = 0; i < NF4A; i++) {
                int f = tid * NF4A + i;
                int row = f >> 2, c4 = (f & 3) << 2;
                int gm = mrow0 + row;
                va[i] = (gm < M) ? *(const float4*)(A + (size_t)gm * lda + k0 + c4) : Z4;
            }
#pragma unroll
            for (int i = 0; i < 4; i++) {
                int f = tid * 4 + i;
                int row = f >> 2, c4 = (f & 3) << 2;
                int gn = nrow0 + row;
                vb[i] = (gn < N) ? *(const float4*)(B + (size_t)gn * ldb + k0 + c4) : Z4;
            }
        }

        {
            uint32_t ah[4][4], al_[4][4], bh[JT][2], bl_[JT][2];
#pragma unroll
            for (int i = 0; i < 4; i++) {
                uint32_t ao = (uint32_t)(i * 16 * SST * 2);
                ldsm4(ah[i][0],  ah[i][1],  ah[i][2],  ah[i][3],  uAh + ao);
                ldsm4(al_[i][0], al_[i][1], al_[i][2], al_[i][3], uAl + ao);
            }
#pragma unroll
            for (int jp = 0; jp < JT / 2; jp++) {
                uint32_t bo = (uint32_t)(jp * 16 * SST * 2);
                ldsm4(bh[jp*2][0],  bh[jp*2][1],  bh[jp*2+1][0],  bh[jp*2+1][1],  uBh + bo);
                ldsm4(bl_[jp*2][0], bl_[jp*2][1], bl_[jp*2+1][0], bl_[jp*2+1][1], uBl + bo);
            }
#pragma unroll
            for (int i = 0; i < 4; i++)
#pragma unroll
                for (int j = 0; j < JT; j++) mma16816(acc[i][j], ah[i], bh[j]);
#pragma unroll
            for (int i = 0; i < 4; i++)
#pragma unroll
                for (int j = 0; j < JT; j++) mma16816(acc[i][j], ah[i], bl_[j]);
#pragma unroll
            for (int i = 0; i < 4; i++)
#pragma unroll
                for (int j = 0; j < JT; j++) mma16816(acc[i][j], al_[i], bh[j]);
        }
        __syncthreads();
    }

    // ---------------- epilogue ----------------
    if (mode == 2) {
#pragma unroll
        for (int i = 0; i < 4; i++) {
            int r1 = mrow0 + wm * 64 + i * 16 + g;
            int r2 = r1 + 8;
            int b1 = r1 & (Bsz - 1), t1 = r1 >> 6;
            int b2 = r2 & (Bsz - 1), t2 = r2 >> 6;
            float p1 = 0.f, p2 = 0.f;
#pragma unroll
            for (int j = 0; j < JT; j++) {
#pragma unroll
                for (int c = 0; c < 2; c++) {
                    int col = nrow0 + wn * WTN + j * 8 + tg * 2 + c;
                    float vv = vvec[col], bb = bias[col];
                    p1 = fmaf(vv, tanhf(acc[i][j][c]     + qadd[(size_t)b1 * N + col] + bb), p1);
                    p2 = fmaf(vv, tanhf(acc[i][j][2 + c] + qadd[(size_t)b2 * N + col] + bb), p2);
                }
            }
            p1 += __shfl_xor_sync(0xffffffffu, p1, 1);
            p1 += __shfl_xor_sync(0xffffffffu, p1, 2);
            p2 += __shfl_xor_sync(0xffffffffu, p2, 1);
            p2 += __shfl_xor_sync(0xffffffffu, p2, 2);
            if (tg == 0) {
                atomicAdd(&score[b1 * T + t1], p1);
                atomicAdd(&score[b2 * T + t2], p2);
            }
        }
    } else {
#pragma unroll
        for (int i = 0; i < 4; i++) {
            int r1 = mrow0 + wm * 64 + i * 16 + g;
            int r2 = r1 + 8;
#pragma unroll
            for (int j = 0; j < JT; j++) {
                int col = nrow0 + wn * WTN + j * 8 + tg * 2;
                if (r1 < M) {
                    size_t ix = (size_t)r1 * ldc + col;
                    if (col < N)     C[ix]     = (mode ? C[ix]     : 0.f) + acc[i][j][0];
                    if (col + 1 < N) C[ix + 1] = (mode ? C[ix + 1] : 0.f) + acc[i][j][1];
                }
                if (r2 < M) {
                    size_t ix = (size_t)r2 * ldc + col;
                    if (col < N)     C[ix]     = (mode ? C[ix]     : 0.f) + acc[i][j][2];
                    if (col + 1 < N) C[ix + 1] = (mode ? C[ix + 1] : 0.f) + acc[i][j][3];
                }
            }
        }
    }
}

// ================= elementwise / reduction kernels =================
__device__ __forceinline__ float warp_reduce_sum(float v) {
#pragma unroll
    for (int o = 16; o > 0; o >>= 1) v += __shfl_xor_sync(0xffffffffu, v, o);
    return v;
}
__device__ __forceinline__ float warp_reduce_max(float v) {
#pragma unroll
    for (int o = 16; o > 0; o >>= 1) v = fmaxf(v, __shfl_xor_sync(0xffffffffu, v, o));
    return v;
}
__device__ float block_reduce_sum(float v) {
    __shared__ float sm[32];
    int tid = threadIdx.x, lane = tid & 31, w = tid >> 5;
    __syncthreads();
    v = warp_reduce_sum(v);
    if (lane == 0) sm[w] = v;
    __syncthreads();
    int nw = (blockDim.x + 31) >> 5;
    v = (tid < nw) ? sm[tid] : 0.f;
    if (w == 0) v = warp_reduce_sum(v);
    if (tid == 0) sm[0] = v;
    __syncthreads();
    return sm[0];
}
__device__ float block_reduce_max(float v) {
    __shared__ float sm[32];
    int tid = threadIdx.x, lane = tid & 31, w = tid >> 5;
    __syncthreads();
    v = warp_reduce_max(v);
    if (lane == 0) sm[w] = v;
    __syncthreads();
    int nw = (blockDim.x + 31) >> 5;
    v = (tid < nw) ? sm[tid] : -3.0e38f;
    if (w == 0) v = warp_reduce_max(v);
    if (tid == 0) sm[0] = v;
    __syncthreads();
    return sm[0];
}

__global__ void embed_kernel(const int* __restrict__ input,
                             const float* __restrict__ embed,
                             float* __restrict__ out)
{
    int b = blockIdx.x;
    int e = threadIdx.x;
    out[b * Ee + e] = embed[(size_t)input[b] * Ee + e];
}

__global__ __launch_bounds__(256) void score_doc_kernel(
    const float* __restrict__ eh, const float* __restrict__ qh,
    const float* __restrict__ bias, const float* __restrict__ v,
    float* __restrict__ score)
{
    int m = blockIdx.x;
    int t = m >> 6;
    int b = m & (Bsz - 1);
    int tid = threadIdx.x;
    const float4* e4 = (const float4*)(eh + (size_t)m * Hh);
    const float4* q4 = (const float4*)(qh + (size_t)b * Hh);
    const float4* b4 = (const float4*)bias;
    const float4* v4 = (const float4*)v;
    float4 ev = e4[tid], qv = q4[tid], bv = b4[tid], vv = v4[tid];
    float s = vv.x * tanhf(ev.x + qv.x + bv.x)
            + vv.y * tanhf(ev.y + qv.y + bv.y)
            + vv.z * tanhf(ev.z + qv.z + bv.z)
            + vv.w * tanhf(ev.w + qv.w + bv.w);
    s = block_reduce_sum(s);
    if (tid == 0) score[b * LDv + t] = s;
}

__global__ __launch_bounds__(128) void softmax_kernel(float* __restrict__ s, int T)
{
    float* x = s + (size_t)blockIdx.x * T;
    float m = -3.0e38f;
    for (int t = threadIdx.x; t < T; t += blockDim.x) m = fmaxf(m, x[t]);
    m = block_reduce_max(m);
    float sum = 0.f;
    for (int t = threadIdx.x; t < T; t += blockDim.x) sum += expf(x[t] - m);
    sum = block_reduce_sum(sum);
    float inv = 1.f / sum;
    for (int t = threadIdx.x; t < T; t += blockDim.x) x[t] = expf(x[t] - m) * inv;
}

__global__ __launch_bounds__(256) void ctx_kernel(
    const float* __restrict__ w, const float* __restrict__ enc,
    float* __restrict__ ctx, int T)
{
    __shared__ float ws[LDv];
    int b = blockIdx.y;
    int h = blockIdx.x * blockDim.x + threadIdx.x;
    for (int t = threadIdx.x; t < T; t += blockDim.x) ws[t] = w[(size_t)b * T + t];
    __syncthreads();
    float acc = 0.f;
    for (int t = 0; t < T; t++)
        acc = fmaf(ws[t], enc[((size_t)t * Bsz + b) * Hh + h], acc);
    ctx[(size_t)b * Hh + h] = acc;
}

__global__ __launch_bounds__(256) void lstm_kernel(
    const float* __restrict__ gates, const float* __restrict__ bi,
    const float* __restrict__ bh, const float* __restrict__ cprev,
    float* __restrict__ hout, float* __restrict__ cout)
{
    int idx = blockIdx.x * blockDim.x + threadIdx.x;
    if (idx >= Bsz * Hh) return;
    int b = idx >> 10;
    int j = idx & (Hh - 1);
    const float* g = gates + (size_t)b * 4 * Hh;
    float gi = g[j]          + bi[j]          + bh[j];
    float gf = g[Hh + j]     + bi[Hh + j]     + bh[Hh + j];
    float gg = g[2 * Hh + j] + bi[2 * Hh + j] + bh[2 * Hh + j];
    float go = g[3 * Hh + j] + bi[3 * Hh + j] + bh[3 * Hh + j];
    float si = 1.f / (1.f + expf(-gi));
    float sf = 1.f / (1.f + expf(-gf));
    float so = 1.f / (1.f + expf(-go));
    float c = sf * cprev[idx] + si * tanhf(gg);
    cout[idx] = c;
    hout[idx] = so * tanhf(c);
}

__global__ void concat2k(const float* __restrict__ a, int wa,
                         const float* __restrict__ b, int wb,
                         float* __restrict__ o, int rows)
{
    int W = wa + wb;
    int idx = blockIdx.x * blockDim.x + threadIdx.x;
    if (idx >= rows * W) return;
    int r = idx / W, j = idx - r * W;
    o[idx] = (j < wa) ? a[(size_t)r * wa + j] : b[(size_t)r * wb + (j - wa)];
}

__global__ __launch_bounds__(512) void logsoftmax_kernel(
    float* __restrict__ logits, const float* __restrict__ bias)
{
    float* x = logits + (size_t)blockIdx.x * Vv;
    int tid = threadIdx.x;
    float m = -3.0e38f;
    for (int v = tid; v < Vv; v += blockDim.x) m = fmaxf(m, x[v] + bias[v]);
    m = block_reduce_max(m);
    float s = 0.f;
    for (int v = tid; v < Vv; v += blockDim.x) s += expf(x[v] + bias[v] - m);
    s = block_reduce_sum(s);
    float lse = m + logf(s);
    for (int v = tid; v < Vv; v += blockDim.x) x[v] = x[v] + bias[v] - lse;
}

// ================= host =================
static inline void tcg_s(cudaStream_t st,
                         const float* A, int lda, const float* B, int ldb,
                         float* C, int ldc, int M, int N, int K, int mode,
                         const float* qadd = nullptr, const float* bias = nullptr,
                         const float* vvec = nullptr, float* score = nullptr, int T = 0)
{
    if (M <= 64) {
        dim3 grid((N + 127) / 128, 1);
        hgemm<1, 3><<<grid, 128, 0, st>>>(A, lda, B, ldb, C, ldc, M, N, K, mode,
                                          qadd, bias, vvec, score, T);
    } else {
        dim3 grid((N + 127) / 128, (M + 127) / 128);
        hgemm<2, 2><<<grid, 128, 0, st>>>(A, lda, B, ldb, C, ldc, M, N, K, mode,
                                          qadd, bias, vvec, score, T);
    }
}

extern "C" void kernel_launch(void* const* d_in, const int* in_sizes, int n_in,
                              void* d_out, int out_size)
{
    const int*   input = (const int*)  d_in[0];
    const float* h0    = (const float*)d_in[1];
    const float* c0    = (const float*)d_in[2];
    const float* dh0   = (const float*)d_in[3];
    const float* dc0   = (const float*)d_in[4];
    const float* qenc  = (const float*)d_in[5];
    const float* denc  = (const float*)d_in[6];
    const float* embed = (const float*)d_in[7];
    const float* W_qa  = (const float*)d_in[8];
    const float* b_qa  = (const float*)d_in[9];
    const float* v_q   = (const float*)d_in[10];
    const float* W_da  = (const float*)d_in[11];
    const float* b_da  = (const float*)d_in[12];
    const float* v_d   = (const float*)d_in[13];
    const float* W_ih  = (const float*)d_in[14];
    const float* W_hh  = (const float*)d_in[15];
    const float* b_ih  = (const float*)d_in[16];
    const float* b_hh  = (const float*)d_in[17];
    const float* Wd_ih = (const float*)d_in[18];
    const float* Wd_hh = (const float*)d_in[19];
    const float* bd_ih = (const float*)d_in[20];
    const float* bd_hh = (const float*)d_in[21];
    const float* W_out = (const float*)d_in[22];
    const float* b_out = (const float*)d_in[23];

    float* out        = (float*)d_out;
    float* out_logits = out;
    float* out_h1     = out + (size_t)Bsz * Vv;
    float* out_c1     = out_h1 + (size_t)Bsz * Hh;
    float* out_dh     = out_c1 + (size_t)Bsz * Hh;
    float* out_dc     = out_dh + (size_t)Bsz * Hh;
    float* out_docw   = out_dc + (size_t)Bsz * Hh;

    float *p_emb, *p_qh, *p_scoreq, *p_ctxq, *p_dq, *p_dqh, *p_ehd, *p_ctxd,
          *p_gates, *p_dgates, *p_rnn;
    cudaGetSymbolAddress((void**)&p_emb,    g_embedded);
    cudaGetSymbolAddress((void**)&p_qh,     g_qh);
    cudaGetSymbolAddress((void**)&p_scoreq, g_scoreq);
    cudaGetSymbolAddress((void**)&p_ctxq,   g_ctxq);
    cudaGetSymbolAddress((void**)&p_dq,     g_dq);
    cudaGetSymbolAddress((void**)&p_dqh,    g_dqh);
    cudaGetSymbolAddress((void**)&p_ehd,    g_ehd);
    cudaGetSymbolAddress((void**)&p_ctxd,   g_ctxd);
    cudaGetSymbolAddress((void**)&p_gates,  g_gates);
    cudaGetSymbolAddress((void**)&p_dgates, g_dgates);
    cudaGetSymbolAddress((void**)&p_rnn,    g_rnn);

    static cudaStream_t s2 = nullptr;
    static cudaEvent_t evF1, evB1, evF2, evB2;
    if (s2 == nullptr) {
        cudaStreamCreateWithFlags(&s2, cudaStreamNonBlocking);
        cudaEventCreateWithFlags(&evF1, cudaEventDisableTiming);
        cudaEventCreateWithFlags(&evB1, cudaEventDisableTiming);
        cudaEventCreateWithFlags(&evF2, cudaEventDisableTiming);
        cudaEventCreateWithFlags(&evB2, cudaEventDisableTiming);
    }
    cudaStream_t s0 = 0;

    // ---- fork 1: big doc-energy GEMM overlaps the query chain ----
    cudaEventRecord(evF1, s0);
    cudaStreamWaitEvent(s2, evF1, 0);
    tcg_s(s2, denc, Hh, W_da + 2 * Hh, 3 * Hh, p_ehd, Hh, LDv * Bsz, Hh, Hh, 0);
    cudaEventRecord(evB1, s2);

    embed_kernel<<<Bsz, Ee, 0, s0>>>(input, embed, p_emb);
    cudaMemsetAsync(p_scoreq, 0, Bsz * LQv * sizeof(float), s0);
    tcg_s(s0, h0, Hh, W_qa, 2 * Hh, p_qh, Hh, Bsz, Hh, Hh, 0);
    tcg_s(s0, qenc, Hh, W_qa + Hh, 2 * Hh, nullptr, 0, LQv * Bsz, Hh, Hh, 2,
          p_qh, b_qa, v_q, p_scoreq, LQv);
    softmax_kernel<<<Bsz, 128, 0, s0>>>(p_scoreq, LQv);
    ctx_kernel<<<dim3(Hh / 256, Bsz), 256, 0, s0>>>(p_scoreq, qenc, p_ctxq, LQv);
    concat2k<<<(Bsz * 2 * Hh + 255) / 256, 256, 0, s0>>>(h0, Hh, p_ctxq, Hh, p_dq, Bsz);
    tcg_s(s0, p_dq, 2 * Hh, W_da, 3 * Hh, p_dqh, Hh, Bsz, Hh, 2 * Hh, 0);

    // ---- join 1 ----
    cudaStreamWaitEvent(s0, evB1, 0);
    score_doc_kernel<<<LDv * Bsz, 256, 0, s0>>>(p_ehd, p_dqh, b_da, v_d, out_docw);
    softmax_kernel<<<Bsz, 128, 0, s0>>>(out_docw, LDv);
    ctx_kernel<<<dim3(Hh / 256, Bsz), 256, 0, s0>>>(out_docw, denc, p_ctxd, LDv);

    // ---- fork 2: ctx half of output projection overlaps the LSTM chain ----
    cudaEventRecord(evF2, s0);
    cudaStreamWaitEvent(s2, evF2, 0);
    tcg_s(s2, p_ctxd, Hh, W_out + Hh, 2 * Hh, out_logits, Vv, Bsz, Vv, Hh, 0);
    cudaEventRecord(evB2, s2);

    tcg_s(s0, p_ctxd, Hh, Wd_ih, Hh, p_dgates, 4 * Hh, Bsz, 4 * Hh, Hh, 0);
    tcg_s(s0, dh0,    Hh, Wd_hh, Hh, p_dgates, 4 * Hh, Bsz, 4 * Hh, Hh, 1);
    lstm_kernel<<<(Bsz * Hh + 255) / 256, 256, 0, s0>>>(p_dgates, bd_ih, bd_hh, dc0, out_dh, out_dc);
    concat2k<<<(Bsz * (Hh + Ee) + 255) / 256, 256, 0, s0>>>(p_emb, Ee, p_ctxd, Hh, p_rnn, Bsz);
    tcg_s(s0, p_rnn, Hh + Ee, W_ih, Hh + Ee, p_gates, 4 * Hh, Bsz, 4 * Hh, Hh + Ee, 0);
    tcg_s(s0, h0,    Hh,      W_hh, Hh,      p_gates, 4 * Hh, Bsz, 4 * Hh, Hh, 1);
    lstm_kernel<<<(Bsz * Hh + 255) / 256, 256, 0, s0>>>(p_gates, b_ih, b_hh, c0, out_h1, out_c1);

    // ---- join 2 ----
    cudaStreamWaitEvent(s0, evB2, 0);
    tcg_s(s0, out_h1, Hh, W_out, 2 * Hh, out_logits, Vv, Bsz, Vv, Hh, 1);
    logsoftmax_kernel<<<Bsz, 512, 0, s0>>>(out_logits, b_out);
}

// round 15
// speedup vs baseline: 1.3949x; 1.3949x over previous
#include <cuda_runtime.h>
#include <cuda_bf16.h>
#include <stdint.h>
#include <math.h>

#define Bsz 64
#define Vv  50000
#define Ee  512
#define Hh  1024
#define LQv 32
#define LDv 400

// ---------------- scratch ----------------
__device__ float g_embedded[Bsz * Ee];
__device__ float g_qh[Bsz * Hh];
__device__ float g_scoreq[Bsz * LQv];
__device__ float g_ctxq[Bsz * Hh];
__device__ float g_dq[Bsz * 2 * Hh];
__device__ float g_dqh[Bsz * Hh];
__device__ float g_ehd[(size_t)LDv * Bsz * Hh];   // ~105 MB
__device__ float g_ctxd[Bsz * Hh];
__device__ float g_gates[Bsz * 4 * Hh];
__device__ float g_dgates[Bsz * 4 * Hh];
__device__ float g_rnn[Bsz * (Hh + Ee)];

// ================= HMMA bf16 split-precision GEMM (R13 + double-buffer) ==========
#define SSTR 40

__device__ __forceinline__ void mma16816(float* d, const uint32_t* a, const uint32_t* b) {
    asm volatile(
        "mma.sync.aligned.m16n8k16.row.col.f32.bf16.bf16.f32 "
        "{%0,%1,%2,%3}, {%4,%5,%6,%7}, {%8,%9}, {%0,%1,%2,%3};"
        : "+f"(d[0]), "+f"(d[1]), "+f"(d[2]), "+f"(d[3])
        : "r"(a[0]), "r"(a[1]), "r"(a[2]), "r"(a[3]), "r"(b[0]), "r"(b[1]));
}

__device__ __forceinline__ void ldsm4(uint32_t& r0, uint32_t& r1, uint32_t& r2, uint32_t& r3,
                                      uint32_t addr) {
    asm volatile("ldmatrix.sync.aligned.m8n8.x4.shared.b16 {%0,%1,%2,%3}, [%4];"
                 : "=r"(r0), "=r"(r1), "=r"(r2), "=r"(r3) : "r"(addr));
}

__device__ __forceinline__ uint32_t s2u(const void* p) {
    uint32_t a;
    asm("{ .reg .u64 t; cvta.to.shared.u64 t, %1; cvt.u32.u64 %0, t; }" : "=r"(a) : "l"(p));
    return a;
}

__device__ __forceinline__ void cvt_store(uint16_t* hi, uint16_t* lo, int off, float4 v) {
    __nv_bfloat162 h01 = __floats2bfloat162_rn(v.x, v.y);
    __nv_bfloat162 h23 = __floats2bfloat162_rn(v.z, v.w);
    float2 f01 = __bfloat1622float2(h01);
    float2 f23 = __bfloat1622float2(h23);
    __nv_bfloat162 l01 = __floats2bfloat162_rn(v.x - f01.x, v.y - f01.y);
    __nv_bfloat162 l23 = __floats2bfloat162_rn(v.z - f23.x, v.w - f23.y);
    *(uint2*)(hi + off) = make_uint2(*(uint32_t*)&h01, *(uint32_t*)&h23);
    *(uint2*)(lo + off) = make_uint2(*(uint32_t*)&l01, *(uint32_t*)&l23);
}

// WI=2 (BM=64), OCC=2, double-buffered smem, ONE barrier per slab.
template <int WI, int OCC>
__global__ __launch_bounds__(256, OCC) void hgemm(
    const float* __restrict__ A, int lda,
    const float* __restrict__ B, int ldb,
    float* __restrict__ C, int ldc,
    int M, int N, int K, int mode,
    const float* __restrict__ qadd, const float* __restrict__ bias,
    const float* __restrict__ vvec, float* __restrict__ score, int T)
{
    const int BM = WI * 32;
    const int AU = BM * SSTR;
    const int BU = 128 * SSTR;
    __shared__ __align__(16) uint16_t Asm[2][2 * (64 * SSTR)];   // [buf][hi|lo]
    __shared__ __align__(16) uint16_t Bsm[2][2 * (128 * SSTR)];

    int tid  = threadIdx.x;
    int lane = tid & 31;
    int w    = tid >> 5;
    int g    = lane >> 2;
    int tg   = lane & 3;
    int wm   = w >> 2;
    int wn   = w & 3;

    int mrow0 = blockIdx.y * BM;
    int nrow0 = blockIdx.x * 128;

    int r0 = tid >> 3;
    int c4 = (tid & 7) << 2;

    uint32_t aoff = (uint32_t)((wm * (WI * 16) + (lane & 15)) * SSTR * 2 + ((lane >> 4) & 1) * 16);
    uint32_t boff = (uint32_t)((wn * 32 + ((lane >> 4) & 1) * 8 + (lane & 7)) * SSTR * 2 + ((lane >> 3) & 1) * 16);

    float acc[WI][4][4];
#pragma unroll
    for (int i = 0; i < WI; i++)
#pragma unroll
        for (int j = 0; j < 4; j++)
#pragma unroll
            for (int q = 0; q < 4; q++) acc[i][j][q] = 0.f;

    const float4 Z4 = make_float4(0.f, 0.f, 0.f, 0.f);
    float4 va[WI], vb[4];
#pragma unroll
    for (int it = 0; it < WI; it++) {
        int gm = mrow0 + r0 + it * 32;
        va[it] = (gm < M) ? *(const float4*)(A + (size_t)gm * lda + c4) : Z4;
    }
#pragma unroll
    for (int it = 0; it < 4; it++) {
        int gn = nrow0 + r0 + it * 32;
        vb[it] = (gn < N) ? *(const float4*)(B + (size_t)gn * ldb + c4) : Z4;
    }

    int ns = K >> 5;
    for (int s = 0; s < ns; s++) {
        int bsel = s & 1;
        uint16_t* Ah = Asm[bsel];
        uint16_t* Al = Ah + AU;
        uint16_t* Bh = Bsm[bsel];
        uint16_t* Bl = Bh + BU;
#pragma unroll
        for (int it = 0; it < WI; it++)
            cvt_store(Ah, Al, (r0 + it * 32) * SSTR + c4, va[it]);
#pragma unroll
        for (int it = 0; it < 4; it++)
            cvt_store(Bh, Bl, (r0 + it * 32) * SSTR + c4, vb[it]);
        __syncthreads();   // buf[bsel] ready; also guarantees prior MMA on buf[bsel^1] done

        if (s + 1 < ns) {
            int k0 = (s + 1) << 5;
#pragma unroll
            for (int it = 0; it < WI; it++) {
                int gm = mrow0 + r0 + it * 32;
                va[it] = (gm < M) ? *(const float4*)(A + (size_t)gm * lda + k0 + c4) : Z4;
            }
#pragma unroll
            for (int it = 0; it < 4; it++) {
                int gn = nrow0 + r0 + it * 32;
                vb[it] = (gn < N) ? *(const float4*)(B + (size_t)gn * ldb + k0 + c4) : Z4;
            }
        }

        uint32_t uAh = s2u(Ah) + aoff, uAl = s2u(Al) + aoff;
        uint32_t uBh = s2u(Bh) + boff, uBl = s2u(Bl) + boff;
#pragma unroll
        for (int ks = 0; ks < 32; ks += 16) {
            uint32_t ksb = (uint32_t)(ks * 2);
            uint32_t ah[WI][4], al_[WI][4], bh[4][2], bl_[4][2];
#pragma unroll
            for (int i = 0; i < WI; i++) {
                uint32_t ao = (uint32_t)(i * 16 * SSTR * 2) + ksb;
                ldsm4(ah[i][0],  ah[i][1],  ah[i][2],  ah[i][3],  uAh + ao);
                ldsm4(al_[i][0], al_[i][1], al_[i][2], al_[i][3], uAl + ao);
            }
#pragma unroll
            for (int jp = 0; jp < 2; jp++) {
                uint32_t bo = (uint32_t)(jp * 16 * SSTR * 2) + ksb;
                ldsm4(bh[jp*2][0],  bh[jp*2][1],  bh[jp*2+1][0],  bh[jp*2+1][1],  uBh + bo);
                ldsm4(bl_[jp*2][0], bl_[jp*2][1], bl_[jp*2+1][0], bl_[jp*2+1][1], uBl + bo);
            }
#pragma unroll
            for (int i = 0; i < WI; i++)
#pragma unroll
                for (int j = 0; j < 4; j++) mma16816(acc[i][j], ah[i], bh[j]);
#pragma unroll
            for (int i = 0; i < WI; i++)
#pragma unroll
                for (int j = 0; j < 4; j++) mma16816(acc[i][j], ah[i], bl_[j]);
#pragma unroll
            for (int i = 0; i < WI; i++)
#pragma unroll
                for (int j = 0; j < 4; j++) mma16816(acc[i][j], al_[i], bh[j]);
        }
        // no trailing barrier: next iteration's barrier protects buffer reuse
    }

    if (mode == 2) {
#pragma unroll
        for (int i = 0; i < WI; i++) {
            int r1 = mrow0 + wm * (WI * 16) + i * 16 + g;
            int r2 = r1 + 8;
            int b1 = r1 & (Bsz - 1), t1 = r1 >> 6;
            int b2 = r2 & (Bsz - 1), t2 = r2 >> 6;
            float p1 = 0.f, p2 = 0.f;
#pragma unroll
            for (int j = 0; j < 4; j++) {
#pragma unroll
                for (int c = 0; c < 2; c++) {
                    int col = nrow0 + wn * 32 + j * 8 + tg * 2 + c;
                    float vv = vvec[col], bb = bias[col];
                    p1 = fmaf(vv, tanhf(acc[i][j][c]     + qadd[(size_t)b1 * N + col] + bb), p1);
                    p2 = fmaf(vv, tanhf(acc[i][j][2 + c] + qadd[(size_t)b2 * N + col] + bb), p2);
                }
            }
            p1 += __shfl_xor_sync(0xffffffffu, p1, 1);
            p1 += __shfl_xor_sync(0xffffffffu, p1, 2);
            p2 += __shfl_xor_sync(0xffffffffu, p2, 1);
            p2 += __shfl_xor_sync(0xffffffffu, p2, 2);
            if (tg == 0) {
                atomicAdd(&score[b1 * T + t1], p1);
                atomicAdd(&score[b2 * T + t2], p2);
            }
        }
    } else {
#pragma unroll
        for (int i = 0; i < WI; i++) {
            int r1 = mrow0 + wm * (WI * 16) + i * 16 + g;
            int r2 = r1 + 8;
#pragma unroll
            for (int j = 0; j < 4; j++) {
                int col = nrow0 + wn * 32 + j * 8 + tg * 2;
                if (r1 < M) {
                    size_t ix = (size_t)r1 * ldc + col;
                    if (col < N)     C[ix]     = (mode ? C[ix]     : 0.f) + acc[i][j][0];
                    if (col + 1 < N) C[ix + 1] = (mode ? C[ix + 1] : 0.f) + acc[i][j][1];
                }
                if (r2 < M) {
                    size_t ix = (size_t)r2 * ldc + col;
                    if (col < N)     C[ix]     = (mode ? C[ix]     : 0.f) + acc[i][j][2];
                    if (col + 1 < N) C[ix + 1] = (mode ? C[ix + 1] : 0.f) + acc[i][j][3];
                }
            }
        }
    }
}

// ================= elementwise / reduction kernels =================
__device__ __forceinline__ float warp_reduce_sum(float v) {
#pragma unroll
    for (int o = 16; o > 0; o >>= 1) v += __shfl_xor_sync(0xffffffffu, v, o);
    return v;
}
__device__ __forceinline__ float warp_reduce_max(float v) {
#pragma unroll
    for (int o = 16; o > 0; o >>= 1) v = fmaxf(v, __shfl_xor_sync(0xffffffffu, v, o));
    return v;
}
__device__ float block_reduce_sum(float v) {
    __shared__ float sm[32];
    int tid = threadIdx.x, lane = tid & 31, w = tid >> 5;
    __syncthreads();
    v = warp_reduce_sum(v);
    if (lane == 0) sm[w] = v;
    __syncthreads();
    int nw = (blockDim.x + 31) >> 5;
    v = (tid < nw) ? sm[tid] : 0.f;
    if (w == 0) v = warp_reduce_sum(v);
    if (tid == 0) sm[0] = v;
    __syncthreads();
    return sm[0];
}
__device__ float block_reduce_max(float v) {
    __shared__ float sm[32];
    int tid = threadIdx.x, lane = tid & 31, w = tid >> 5;
    __syncthreads();
    v = warp_reduce_max(v);
    if (lane == 0) sm[w] = v;
    __syncthreads();
    int nw = (blockDim.x + 31) >> 5;
    v = (tid < nw) ? sm[tid] : -3.0e38f;
    if (w == 0) v = warp_reduce_max(v);
    if (tid == 0) sm[0] = v;
    __syncthreads();
    return sm[0];
}

__global__ void embed_kernel(const int* __restrict__ input,
                             const float* __restrict__ embed,
                             float* __restrict__ out)
{
    int b = blockIdx.x;
    int e = threadIdx.x;
    out[b * Ee + e] = embed[(size_t)input[b] * Ee + e];
}

__global__ __launch_bounds__(256) void score_doc_kernel(
    const float* __restrict__ eh, const float* __restrict__ qh,
    const float* __restrict__ bias, const float* __restrict__ v,
    float* __restrict__ score)
{
    int m = blockIdx.x;
    int t = m >> 6;
    int b = m & (Bsz - 1);
    int tid = threadIdx.x;
    const float4* e4 = (const float4*)(eh + (size_t)m * Hh);
    const float4* q4 = (const float4*)(qh + (size_t)b * Hh);
    const float4* b4 = (const float4*)bias;
    const float4* v4 = (const float4*)v;
    float4 ev = e4[tid], qv = q4[tid], bv = b4[tid], vv = v4[tid];
    float s = vv.x * tanhf(ev.x + qv.x + bv.x)
            + vv.y * tanhf(ev.y + qv.y + bv.y)
            + vv.z * tanhf(ev.z + qv.z + bv.z)
            + vv.w * tanhf(ev.w + qv.w + bv.w);
    s = block_reduce_sum(s);
    if (tid == 0) score[b * LDv + t] = s;
}

__global__ __launch_bounds__(128) void softmax_kernel(float* __restrict__ s, int T)
{
    float* x = s + (size_t)blockIdx.x * T;
    float m = -3.0e38f;
    for (int t = threadIdx.x; t < T; t += blockDim.x) m = fmaxf(m, x[t]);
    m = block_reduce_max(m);
    float sum = 0.f;
    for (int t = threadIdx.x; t < T; t += blockDim.x) sum += expf(x[t] - m);
    sum = block_reduce_sum(sum);
    float inv = 1.f / sum;
    for (int t = threadIdx.x; t < T; t += blockDim.x) x[t] = expf(x[t] - m) * inv;
}

__global__ __launch_bounds__(256) void ctx_kernel(
    const float* __restrict__ w, const float* __restrict__ enc,
    float* __restrict__ ctx, int T)
{
    __shared__ float ws[LDv];
    int b = blockIdx.y;
    int h = blockIdx.x * blockDim.x + threadIdx.x;
    for (int t = threadIdx.x; t < T; t += blockDim.x) ws[t] = w[(size_t)b * T + t];
    __syncthreads();
    float acc = 0.f;
    for (int t = 0; t < T; t++)
        acc = fmaf(ws[t], enc[((size_t)t * Bsz + b) * Hh + h], acc);
    ctx[(size_t)b * Hh + h] = acc;
}

__global__ __launch_bounds__(256) void lstm_kernel(
    const float* __restrict__ gates, const float* __restrict__ bi,
    const float* __restrict__ bh, const float* __restrict__ cprev,
    float* __restrict__ hout, float* __restrict__ cout)
{
    int idx = blockIdx.x * blockDim.x + threadIdx.x;
    if (idx >= Bsz * Hh) return;
    int b = idx >> 10;
    int j = idx & (Hh - 1);
    const float* g = gates + (size_t)b * 4 * Hh;
    float gi = g[j]          + bi[j]          + bh[j];
    float gf = g[Hh + j]     + bi[Hh + j]     + bh[Hh + j];
    float gg = g[2 * Hh + j] + bi[2 * Hh + j] + bh[2 * Hh + j];
    float go = g[3 * Hh + j] + bi[3 * Hh + j] + bh[3 * Hh + j];
    float si = 1.f / (1.f + expf(-gi));
    float sf = 1.f / (1.f + expf(-gf));
    float so = 1.f / (1.f + expf(-go));
    float c = sf * cprev[idx] + si * tanhf(gg);
    cout[idx] = c;
    hout[idx] = so * tanhf(c);
}

__global__ void concat2k(const float* __restrict__ a, int wa,
                         const float* __restrict__ b, int wb,
                         float* __restrict__ o, int rows)
{
    int W = wa + wb;
    int idx = blockIdx.x * blockDim.x + threadIdx.x;
    if (idx >= rows * W) return;
    int r = idx / W, j = idx - r * W;
    o[idx] = (j < wa) ? a[(size_t)r * wa + j] : b[(size_t)r * wb + (j - wa)];
}

__global__ __launch_bounds__(512) void logsoftmax_kernel(
    float* __restrict__ logits, const float* __restrict__ bias)
{
    float* x = logits + (size_t)blockIdx.x * Vv;
    int tid = threadIdx.x;
    float m = -3.0e38f;
    for (int v = tid; v < Vv; v += blockDim.x) m = fmaxf(m, x[v] + bias[v]);
    m = block_reduce_max(m);
    float s = 0.f;
    for (int v = tid; v < Vv; v += blockDim.x) s += expf(x[v] + bias[v] - m);
    s = block_reduce_sum(s);
    float lse = m + logf(s);
    for (int v = tid; v < Vv; v += blockDim.x) x[v] = x[v] + bias[v] - lse;
}

// ================= host =================
static inline void tcg_s(cudaStream_t st,
                         const float* A, int lda, const float* B, int ldb,
                         float* C, int ldc, int M, int N, int K, int mode,
                         const float* qadd = nullptr, const float* bias = nullptr,
                         const float* vvec = nullptr, float* score = nullptr, int T = 0)
{
    dim3 grid((N + 127) / 128, (M + 63) / 64);
    hgemm<2, 2><<<grid, 256, 0, st>>>(A, lda, B, ldb, C, ldc, M, N, K, mode,
                                      qadd, bias, vvec, score, T);
}

extern "C" void kernel_launch(void* const* d_in, const int* in_sizes, int n_in,
                              void* d_out, int out_size)
{
    const int*   input = (const int*)  d_in[0];
    const float* h0    = (const float*)d_in[1];
    const float* c0    = (const float*)d_in[2];
    const float* dh0   = (const float*)d_in[3];
    const float* dc0   = (const float*)d_in[4];
    const float* qenc  = (const float*)d_in[5];
    const float* denc  = (const float*)d_in[6];
    const float* embed = (const float*)d_in[7];
    const float* W_qa  = (const float*)d_in[8];
    const float* b_qa  = (const float*)d_in[9];
    const float* v_q   = (const float*)d_in[10];
    const float* W_da  = (const float*)d_in[11];
    const float* b_da  = (const float*)d_in[12];
    const float* v_d   = (const float*)d_in[13];
    const float* W_ih  = (const float*)d_in[14];
    const float* W_hh  = (const float*)d_in[15];
    const float* b_ih  = (const float*)d_in[16];
    const float* b_hh  = (const float*)d_in[17];
    const float* Wd_ih = (const float*)d_in[18];
    const float* Wd_hh = (const float*)d_in[19];
    const float* bd_ih = (const float*)d_in[20];
    const float* bd_hh = (const float*)d_in[21];
    const float* W_out = (const float*)d_in[22];
    const float* b_out = (const float*)d_in[23];

    float* out        = (float*)d_out;
    float* out_logits = out;
    float* out_h1     = out + (size_t)Bsz * Vv;
    float* out_c1     = out_h1 + (size_t)Bsz * Hh;
    float* out_dh     = out_c1 + (size_t)Bsz * Hh;
    float* out_dc     = out_dh + (size_t)Bsz * Hh;
    float* out_docw   = out_dc + (size_t)Bsz * Hh;

    float *p_emb, *p_qh, *p_scoreq, *p_ctxq, *p_dq, *p_dqh, *p_ehd, *p_ctxd,
          *p_gates, *p_dgates, *p_rnn;
    cudaGetSymbolAddress((void**)&p_emb,    g_embedded);
    cudaGetSymbolAddress((void**)&p_qh,     g_qh);
    cudaGetSymbolAddress((void**)&p_scoreq, g_scoreq);
    cudaGetSymbolAddress((void**)&p_ctxq,   g_ctxq);
    cudaGetSymbolAddress((void**)&p_dq,     g_dq);
    cudaGetSymbolAddress((void**)&p_dqh,    g_dqh);
    cudaGetSymbolAddress((void**)&p_ehd,    g_ehd);
    cudaGetSymbolAddress((void**)&p_ctxd,   g_ctxd);
    cudaGetSymbolAddress((void**)&p_gates,  g_gates);
    cudaGetSymbolAddress((void**)&p_dgates, g_dgates);
    cudaGetSymbolAddress((void**)&p_rnn,    g_rnn);

    static cudaStream_t s2 = nullptr, s3 = nullptr;
    static cudaEvent_t evF1, evB1, evF2, evB2, evF3, evB3;
    if (s2 == nullptr) {
        cudaStreamCreateWithFlags(&s2, cudaStreamNonBlocking);
        cudaStreamCreateWithFlags(&s3, cudaStreamNonBlocking);
        cudaEventCreateWithFlags(&evF1, cudaEventDisableTiming);
        cudaEventCreateWithFlags(&evB1, cudaEventDisableTiming);
        cudaEventCreateWithFlags(&evF2, cudaEventDisableTiming);
        cudaEventCreateWithFlags(&evB2, cudaEventDisableTiming);
        cudaEventCreateWithFlags(&evF3, cudaEventDisableTiming);
        cudaEventCreateWithFlags(&evB3, cudaEventDisableTiming);
    }
    cudaStream_t s0 = 0;

    // ---- fork 1: big doc-energy GEMM overlaps the query chain ----
    cudaEventRecord(evF1, s0);
    cudaStreamWaitEvent(s2, evF1, 0);
    tcg_s(s2, denc, Hh, W_da + 2 * Hh, 3 * Hh, p_ehd, Hh, LDv * Bsz, Hh, Hh, 0);
    cudaEventRecord(evB1, s2);

    embed_kernel<<<Bsz, Ee, 0, s0>>>(input, embed, p_emb);
    cudaMemsetAsync(p_scoreq, 0, Bsz * LQv * sizeof(float), s0);
    tcg_s(s0, h0, Hh, W_qa, 2 * Hh, p_qh, Hh, Bsz, Hh, Hh, 0);
    tcg_s(s0, qenc, Hh, W_qa + Hh, 2 * Hh, nullptr, 0, LQv * Bsz, Hh, Hh, 2,
          p_qh, b_qa, v_q, p_scoreq, LQv);
    softmax_kernel<<<Bsz, 128, 0, s0>>>(p_scoreq, LQv);
    ctx_kernel<<<dim3(Hh / 256, Bsz), 256, 0, s0>>>(p_scoreq, qenc, p_ctxq, LQv);
    concat2k<<<(Bsz * 2 * Hh + 255) / 256, 256, 0, s0>>>(h0, Hh, p_ctxq, Hh, p_dq, Bsz);
    tcg_s(s0, p_dq, 2 * Hh, W_da, 3 * Hh, p_dqh, Hh, Bsz, Hh, 2 * Hh, 0);

    // ---- join 1 ----
    cudaStreamWaitEvent(s0, evB1, 0);
    score_doc_kernel<<<LDv * Bsz, 256, 0, s0>>>(p_ehd, p_dqh, b_da, v_d, out_docw);
    softmax_kernel<<<Bsz, 128, 0, s0>>>(out_docw, LDv);
    ctx_kernel<<<dim3(Hh / 256, Bsz), 256, 0, s0>>>(out_docw, denc, p_ctxd, LDv);

    // ---- fork 2: ctx half of output projection + fork 3: distraction LSTM ----
    cudaEventRecord(evF2, s0);
    cudaStreamWaitEvent(s2, evF2, 0);
    tcg_s(s2, p_ctxd, Hh, W_out + Hh, 2 * Hh, out_logits, Vv, Bsz, Vv, Hh, 0);
    cudaEventRecord(evB2, s2);

    cudaStreamWaitEvent(s3, evF2, 0);
    tcg_s(s3, p_ctxd, Hh, Wd_ih, Hh, p_dgates, 4 * Hh, Bsz, 4 * Hh, Hh, 0);
    tcg_s(s3, dh0,    Hh, Wd_hh, Hh, p_dgates, 4 * Hh, Bsz, 4 * Hh, Hh, 1);
    lstm_kernel<<<(Bsz * Hh + 255) / 256, 256, 0, s3>>>(p_dgates, bd_ih, bd_hh, dc0, out_dh, out_dc);
    cudaEventRecord(evB3, s3);

    // ---- s0: main LSTM chain ----
    concat2k<<<(Bsz * (Hh + Ee) + 255) / 256, 256, 0, s0>>>(p_emb, Ee, p_ctxd, Hh, p_rnn, Bsz);
    tcg_s(s0, p_rnn, Hh + Ee, W_ih, Hh + Ee, p_gates, 4 * Hh, Bsz, 4 * Hh, Hh + Ee, 0);
    tcg_s(s0, h0,    Hh,      W_hh, Hh,      p_gates, 4 * Hh, Bsz, 4 * Hh, Hh, 1);
    lstm_kernel<<<(Bsz * Hh + 255) / 256, 256, 0, s0>>>(p_gates, b_ih, b_hh, c0, out_h1, out_c1);

    // ---- join 2 ----
    cudaStreamWaitEvent(s0, evB2, 0);
    cudaStreamWaitEvent(s0, evB3, 0);
    tcg_s(s0, out_h1, Hh, W_out, 2 * Hh, out_logits, Vv, Bsz, Vv, Hh, 1);
    logsoftmax_kernel<<<Bsz, 512, 0, s0>>>(out_logits, b_out);
}

// round 16
// speedup vs baseline: 1.4328x; 1.0272x over previous
#include <cuda_runtime.h>
#include <cuda_bf16.h>
#include <stdint.h>
#include <math.h>

#define Bsz 64
#define Vv  50000
#define Ee  512
#define Hh  1024
#define LQv 32
#define LDv 400

// ---------------- scratch ----------------
__device__ float g_embedded[Bsz * Ee];
__device__ float g_qh[Bsz * Hh];
__device__ float g_scoreq[Bsz * LQv];
__device__ float g_ctxq[Bsz * Hh];
__device__ float g_dq[Bsz * 2 * Hh];
__device__ float g_dqh[Bsz * Hh];
__device__ float g_ehd[(size_t)LDv * Bsz * Hh];   // ~105 MB
__device__ float g_ctxd[Bsz * Hh];
__device__ float g_gates[Bsz * 4 * Hh];
__device__ float g_dgates[Bsz * 4 * Hh];
__device__ float g_rnn[Bsz * (Hh + Ee)];
// bf16 pre-split operands for the ehd GEMM only
__device__ __align__(16) __nv_bfloat16 g_dencH[(size_t)LDv * Bsz * Hh];
__device__ __align__(16) __nv_bfloat16 g_dencL[(size_t)LDv * Bsz * Hh];
__device__ __align__(16) __nv_bfloat16 g_WdaH[Hh * Hh];
__device__ __align__(16) __nv_bfloat16 g_WdaL[Hh * Hh];

// ================= common asm helpers =================
#define SSTR 40

__device__ __forceinline__ void mma16816(float* d, const uint32_t* a, const uint32_t* b) {
    asm volatile(
        "mma.sync.aligned.m16n8k16.row.col.f32.bf16.bf16.f32 "
        "{%0,%1,%2,%3}, {%4,%5,%6,%7}, {%8,%9}, {%0,%1,%2,%3};"
        : "+f"(d[0]), "+f"(d[1]), "+f"(d[2]), "+f"(d[3])
        : "r"(a[0]), "r"(a[1]), "r"(a[2]), "r"(a[3]), "r"(b[0]), "r"(b[1]));
}
__device__ __forceinline__ void ldsm4(uint32_t& r0, uint32_t& r1, uint32_t& r2, uint32_t& r3,
                                      uint32_t addr) {
    asm volatile("ldmatrix.sync.aligned.m8n8.x4.shared.b16 {%0,%1,%2,%3}, [%4];"
                 : "=r"(r0), "=r"(r1), "=r"(r2), "=r"(r3) : "r"(addr));
}
__device__ __forceinline__ uint32_t s2u(const void* p) {
    uint32_t a;
    asm("{ .reg .u64 t; cvta.to.shared.u64 t, %1; cvt.u32.u64 %0, t; }" : "=r"(a) : "l"(p));
    return a;
}
__device__ __forceinline__ void cpa16(uint32_t dst, const void* src) {
    asm volatile("cp.async.cg.shared.global [%0], [%1], 16;" :: "r"(dst), "l"(src));
}
__device__ __forceinline__ void cpa_commit() {
    asm volatile("cp.async.commit_group;" ::: "memory");
}
__device__ __forceinline__ void cvt_store(uint16_t* hi, uint16_t* lo, int off, float4 v) {
    __nv_bfloat162 h01 = __floats2bfloat162_rn(v.x, v.y);
    __nv_bfloat162 h23 = __floats2bfloat162_rn(v.z, v.w);
    float2 f01 = __bfloat1622float2(h01);
    float2 f23 = __bfloat1622float2(h23);
    __nv_bfloat162 l01 = __floats2bfloat162_rn(v.x - f01.x, v.y - f01.y);
    __nv_bfloat162 l23 = __floats2bfloat162_rn(v.z - f23.x, v.w - f23.y);
    *(uint2*)(hi + off) = make_uint2(*(uint32_t*)&h01, *(uint32_t*)&h23);
    *(uint2*)(lo + off) = make_uint2(*(uint32_t*)&l01, *(uint32_t*)&l23);
}

// ======= operand split: fp32[rows,lds] -> dense bf16 hi/lo [rows,K] =======
__global__ __launch_bounds__(256) void cvt_split(
    const float* __restrict__ src, int lds, int rows, int K,
    __nv_bfloat16* __restrict__ hi, __nv_bfloat16* __restrict__ lo)
{
    size_t i = (size_t)blockIdx.x * blockDim.x + threadIdx.x;
    int kq = K >> 2;
    size_t tot = (size_t)rows * kq;
    if (i >= tot) return;
    int row = (int)(i / kq);
    int c4  = (int)(i - (size_t)row * kq) << 2;
    float4 v = *(const float4*)(src + (size_t)row * lds + c4);
    __nv_bfloat162 h01 = __floats2bfloat162_rn(v.x, v.y);
    __nv_bfloat162 h23 = __floats2bfloat162_rn(v.z, v.w);
    float2 f01 = __bfloat1622float2(h01);
    float2 f23 = __bfloat1622float2(h23);
    __nv_bfloat162 l01 = __floats2bfloat162_rn(v.x - f01.x, v.y - f01.y);
    __nv_bfloat162 l23 = __floats2bfloat162_rn(v.z - f23.x, v.w - f23.y);
    *(uint2*)(hi + (size_t)row * K + c4) = make_uint2(*(uint32_t*)&h01, *(uint32_t*)&h23);
    *(uint2*)(lo + (size_t)row * K + c4) = make_uint2(*(uint32_t*)&l01, *(uint32_t*)&l23);
}

// ======= pure-bf16 GEMM, 3-stage cp.async pipeline (ehd only) =======
// C[M,N] = A*B^T, A/B dense bf16 hi/lo [rows][K]; tiles must be in-bounds;
// K%32==0, K/32>=3. BM=64, BN=128, 8 warps, occ 2 (smem-limited).
#define SM_BF2 (3 * (2 * 64 * SSTR + 2 * 128 * SSTR) * 2)    //  92160 B

__global__ __launch_bounds__(256) void hgemm_bf(
    const __nv_bfloat16* __restrict__ AH, const __nv_bfloat16* __restrict__ AL,
    const __nv_bfloat16* __restrict__ BH, const __nv_bfloat16* __restrict__ BL,
    float* __restrict__ C, int ldc, int M, int N, int K)
{
    const int AU = 64 * SSTR;
    const int BU = 128 * SSTR;
    const int STG = 2 * AU + 2 * BU;
    extern __shared__ __align__(16) uint16_t dsm[];
    uint32_t sbase = s2u(dsm);

    int tid  = threadIdx.x;
    int lane = tid & 31;
    int w    = tid >> 5;
    int g    = lane >> 2;
    int tg   = lane & 3;
    int wm   = w >> 2;
    int wn   = w & 3;

    int mrow0 = blockIdx.y * 64;
    int nrow0 = blockIdx.x * 128;

    uint32_t aoff = (uint32_t)((wm * 32 + (lane & 15)) * SSTR * 2 + ((lane >> 4) & 1) * 16);
    uint32_t boff = (uint32_t)((wn * 32 + ((lane >> 4) & 1) * 8 + (lane & 7)) * SSTR * 2
                               + ((lane >> 3) & 1) * 16);

    float acc[2][4][4];
#pragma unroll
    for (int i = 0; i < 2; i++)
#pragma unroll
        for (int j = 0; j < 4; j++)
#pragma unroll
            for (int q = 0; q < 4; q++) acc[i][j][q] = 0.f;

    auto stage = [&](int s, int st) {
        uint32_t sb = sbase + (uint32_t)(st * STG * 2);
        size_t kc = (size_t)(s << 5);
        {
            int row = tid >> 2, sub = tid & 3;
            uint32_t dst = sb + (uint32_t)(row * 80 + sub * 16);
            cpa16(dst, (const char*)(AH + (size_t)(mrow0 + row) * K + kc) + sub * 16);
            cpa16(dst + AU * 2, (const char*)(AL + (size_t)(mrow0 + row) * K + kc) + sub * 16);
        }
#pragma unroll
        for (int i = 0; i < 2; i++) {
            int c = tid + i * 256;
            int row = c >> 2, sub = c & 3;
            uint32_t dst = sb + (uint32_t)(2 * AU * 2 + row * 80 + sub * 16);
            cpa16(dst, (const char*)(BH + (size_t)(nrow0 + row) * K + kc) + sub * 16);
            cpa16(dst + BU * 2, (const char*)(BL + (size_t)(nrow0 + row) * K + kc) + sub * 16);
        }
    };

    int ns = K >> 5;
    stage(0, 0); cpa_commit();
    stage(1, 1); cpa_commit();
    stage(2, 2); cpa_commit();

    for (int s = 0; s < ns; s++) {
        int st = s % 3;
        asm volatile("cp.async.wait_group 2;" ::: "memory");
        __syncthreads();

        uint32_t sb  = sbase + (uint32_t)(st * STG * 2);
        uint32_t uAh = sb + aoff;
        uint32_t uAl = uAh + AU * 2;
        uint32_t uBh = sb + 2 * AU * 2 + boff;
        uint32_t uBl = uBh + BU * 2;

#pragma unroll
        for (int ks = 0; ks < 32; ks += 16) {
            uint32_t ksb = (uint32_t)(ks * 2);
            uint32_t ah[2][4], al_[2][4], bh[4][2], bl_[4][2];
#pragma unroll
            for (int i = 0; i < 2; i++) {
                uint32_t ao = (uint32_t)(i * 16 * SSTR * 2) + ksb;
                ldsm4(ah[i][0],  ah[i][1],  ah[i][2],  ah[i][3],  uAh + ao);
                ldsm4(al_[i][0], al_[i][1], al_[i][2], al_[i][3], uAl + ao);
            }
#pragma unroll
            for (int jp = 0; jp < 2; jp++) {
                uint32_t bo = (uint32_t)(jp * 16 * SSTR * 2) + ksb;
                ldsm4(bh[jp*2][0],  bh[jp*2][1],  bh[jp*2+1][0],  bh[jp*2+1][1],  uBh + bo);
                ldsm4(bl_[jp*2][0], bl_[jp*2][1], bl_[jp*2+1][0], bl_[jp*2+1][1], uBl + bo);
            }
#pragma unroll
            for (int i = 0; i < 2; i++)
#pragma unroll
                for (int j = 0; j < 4; j++) mma16816(acc[i][j], ah[i], bh[j]);
#pragma unroll
            for (int i = 0; i < 2; i++)
#pragma unroll
                for (int j = 0; j < 4; j++) mma16816(acc[i][j], ah[i], bl_[j]);
#pragma unroll
            for (int i = 0; i < 2; i++)
#pragma unroll
                for (int j = 0; j < 4; j++) mma16816(acc[i][j], al_[i], bh[j]);
        }
        __syncthreads();
        if (s + 3 < ns) stage(s + 3, st);
        cpa_commit();
    }

#pragma unroll
    for (int i = 0; i < 2; i++) {
        int r1 = mrow0 + wm * 32 + i * 16 + g;
        int r2 = r1 + 8;
#pragma unroll
        for (int j = 0; j < 4; j++) {
            int col = nrow0 + wn * 32 + j * 8 + tg * 2;
            size_t ix1 = (size_t)r1 * ldc + col;
            size_t ix2 = (size_t)r2 * ldc + col;
            C[ix1]     = acc[i][j][0];
            C[ix1 + 1] = acc[i][j][1];
            C[ix2]     = acc[i][j][2];
            C[ix2 + 1] = acc[i][j][3];
        }
    }
}

// ================= in-loop-convert GEMM (all other GEMMs; R13 proven) =============
template <int WI, int OCC>
__global__ __launch_bounds__(256, OCC) void hgemm(
    const float* __restrict__ A, int lda,
    const float* __restrict__ B, int ldb,
    float* __restrict__ C, int ldc,
    int M, int N, int K, int mode,
    const float* __restrict__ qadd, const float* __restrict__ bias,
    const float* __restrict__ vvec, float* __restrict__ score, int T)
{
    const int BM = WI * 32;
    __shared__ __align__(16) uint16_t As[2][BM * SSTR];
    __shared__ __align__(16) uint16_t Bs[2][128 * SSTR];
    uint16_t* Ah = As[0];
    uint16_t* Al = As[1];
    uint16_t* Bh = Bs[0];
    uint16_t* Bl = Bs[1];

    int tid  = threadIdx.x;
    int lane = tid & 31;
    int w    = tid >> 5;
    int g    = lane >> 2;
    int tg   = lane & 3;
    int wm   = w >> 2;
    int wn   = w & 3;

    int mrow0 = blockIdx.y * BM;
    int nrow0 = blockIdx.x * 128;

    int r0 = tid >> 3;
    int c4 = (tid & 7) << 2;

    uint32_t aoff = (uint32_t)((wm * (WI * 16) + (lane & 15)) * SSTR * 2 + ((lane >> 4) & 1) * 16);
    uint32_t boff = (uint32_t)((wn * 32 + ((lane >> 4) & 1) * 8 + (lane & 7)) * SSTR * 2 + ((lane >> 3) & 1) * 16);
    uint32_t uAh = s2u(Ah) + aoff, uAl = s2u(Al) + aoff;
    uint32_t uBh = s2u(Bh) + boff, uBl = s2u(Bl) + boff;

    float acc[WI][4][4];
#pragma unroll
    for (int i = 0; i < WI; i++)
#pragma unroll
        for (int j = 0; j < 4; j++)
#pragma unroll
            for (int q = 0; q < 4; q++) acc[i][j][q] = 0.f;

    const float4 Z4 = make_float4(0.f, 0.f, 0.f, 0.f);
    float4 va[WI], vb[4];
#pragma unroll
    for (int it = 0; it < WI; it++) {
        int gm = mrow0 + r0 + it * 32;
        va[it] = (gm < M) ? *(const float4*)(A + (size_t)gm * lda + c4) : Z4;
    }
#pragma unroll
    for (int it = 0; it < 4; it++) {
        int gn = nrow0 + r0 + it * 32;
        vb[it] = (gn < N) ? *(const float4*)(B + (size_t)gn * ldb + c4) : Z4;
    }

    int ns = K >> 5;
    for (int s = 0; s < ns; s++) {
#pragma unroll
        for (int it = 0; it < WI; it++)
            cvt_store(Ah, Al, (r0 + it * 32) * SSTR + c4, va[it]);
#pragma unroll
        for (int it = 0; it < 4; it++)
            cvt_store(Bh, Bl, (r0 + it * 32) * SSTR + c4, vb[it]);
        __syncthreads();

        if (s + 1 < ns) {
            int k0 = (s + 1) << 5;
#pragma unroll
            for (int it = 0; it < WI; it++) {
                int gm = mrow0 + r0 + it * 32;
                va[it] = (gm < M) ? *(const float4*)(A + (size_t)gm * lda + k0 + c4) : Z4;
            }
#pragma unroll
            for (int it = 0; it < 4; it++) {
                int gn = nrow0 + r0 + it * 32;
                vb[it] = (gn < N) ? *(const float4*)(B + (size_t)gn * ldb + k0 + c4) : Z4;
            }
        }

#pragma unroll
        for (int ks = 0; ks < 32; ks += 16) {
            uint32_t ksb = (uint32_t)(ks * 2);
            uint32_t ah[WI][4], al_[WI][4], bh[4][2], bl_[4][2];
#pragma unroll
            for (int i = 0; i < WI; i++) {
                uint32_t ao = (uint32_t)(i * 16 * SSTR * 2) + ksb;
                ldsm4(ah[i][0],  ah[i][1],  ah[i][2],  ah[i][3],  uAh + ao);
                ldsm4(al_[i][0], al_[i][1], al_[i][2], al_[i][3], uAl + ao);
            }
#pragma unroll
            for (int jp = 0; jp < 2; jp++) {
                uint32_t bo = (uint32_t)(jp * 16 * SSTR * 2) + ksb;
                ldsm4(bh[jp*2][0],  bh[jp*2][1],  bh[jp*2+1][0],  bh[jp*2+1][1],  uBh + bo);
                ldsm4(bl_[jp*2][0], bl_[jp*2][1], bl_[jp*2+1][0], bl_[jp*2+1][1], uBl + bo);
            }
#pragma unroll
            for (int i = 0; i < WI; i++)
#pragma unroll
                for (int j = 0; j < 4; j++) mma16816(acc[i][j], ah[i], bh[j]);
#pragma unroll
            for (int i = 0; i < WI; i++)
#pragma unroll
                for (int j = 0; j < 4; j++) mma16816(acc[i][j], ah[i], bl_[j]);
#pragma unroll
            for (int i = 0; i < WI; i++)
#pragma unroll
                for (int j = 0; j < 4; j++) mma16816(acc[i][j], al_[i], bh[j]);
        }
        __syncthreads();
    }

    if (mode == 2) {
#pragma unroll
        for (int i = 0; i < WI; i++) {
            int r1 = mrow0 + wm * (WI * 16) + i * 16 + g;
            int r2 = r1 + 8;
            int b1 = r1 & (Bsz - 1), t1 = r1 >> 6;
            int b2 = r2 & (Bsz - 1), t2 = r2 >> 6;
            float p1 = 0.f, p2 = 0.f;
#pragma unroll
            for (int j = 0; j < 4; j++) {
#pragma unroll
                for (int c = 0; c < 2; c++) {
                    int col = nrow0 + wn * 32 + j * 8 + tg * 2 + c;
                    float vv = vvec[col], bb = bias[col];
                    p1 = fmaf(vv, tanhf(acc[i][j][c]     + qadd[(size_t)b1 * N + col] + bb), p1);
                    p2 = fmaf(vv, tanhf(acc[i][j][2 + c] + qadd[(size_t)b2 * N + col] + bb), p2);
                }
            }
            p1 += __shfl_xor_sync(0xffffffffu, p1, 1);
            p1 += __shfl_xor_sync(0xffffffffu, p1, 2);
            p2 += __shfl_xor_sync(0xffffffffu, p2, 1);
            p2 += __shfl_xor_sync(0xffffffffu, p2, 2);
            if (tg == 0) {
                atomicAdd(&score[b1 * T + t1], p1);
                atomicAdd(&score[b2 * T + t2], p2);
            }
        }
    } else {
#pragma unroll
        for (int i = 0; i < WI; i++) {
            int r1 = mrow0 + wm * (WI * 16) + i * 16 + g;
            int r2 = r1 + 8;
#pragma unroll
            for (int j = 0; j < 4; j++) {
                int col = nrow0 + wn * 32 + j * 8 + tg * 2;
                if (r1 < M) {
                    size_t ix = (size_t)r1 * ldc + col;
                    if (col < N)     C[ix]     = (mode ? C[ix]     : 0.f) + acc[i][j][0];
                    if (col + 1 < N) C[ix + 1] = (mode ? C[ix + 1] : 0.f) + acc[i][j][1];
                }
                if (r2 < M) {
                    size_t ix = (size_t)r2 * ldc + col;
                    if (col < N)     C[ix]     = (mode ? C[ix]     : 0.f) + acc[i][j][2];
                    if (col + 1 < N) C[ix + 1] = (mode ? C[ix + 1] : 0.f) + acc[i][j][3];
                }
            }
        }
    }
}

// ================= elementwise / reduction kernels =================
__device__ __forceinline__ float warp_reduce_sum(float v) {
#pragma unroll
    for (int o = 16; o > 0; o >>= 1) v += __shfl_xor_sync(0xffffffffu, v, o);
    return v;
}
__device__ __forceinline__ float warp_reduce_max(float v) {
#pragma unroll
    for (int o = 16; o > 0; o >>= 1) v = fmaxf(v, __shfl_xor_sync(0xffffffffu, v, o));
    return v;
}
__device__ float block_reduce_sum(float v) {
    __shared__ float sm[32];
    int tid = threadIdx.x, lane = tid & 31, w = tid >> 5;
    __syncthreads();
    v = warp_reduce_sum(v);
    if (lane == 0) sm[w] = v;
    __syncthreads();
    int nw = (blockDim.x + 31) >> 5;
    v = (tid < nw) ? sm[tid] : 0.f;
    if (w == 0) v = warp_reduce_sum(v);
    if (tid == 0) sm[0] = v;
    __syncthreads();
    return sm[0];
}
__device__ float block_reduce_max(float v) {
    __shared__ float sm[32];
    int tid = threadIdx.x, lane = tid & 31, w = tid >> 5;
    __syncthreads();
    v = warp_reduce_max(v);
    if (lane == 0) sm[w] = v;
    __syncthreads();
    int nw = (blockDim.x + 31) >> 5;
    v = (tid < nw) ? sm[tid] : -3.0e38f;
    if (w == 0) v = warp_reduce_max(v);
    if (tid == 0) sm[0] = v;
    __syncthreads();
    return sm[0];
}

__global__ void embed_kernel(const int* __restrict__ input,
                             const float* __restrict__ embed,
                             float* __restrict__ out)
{
    int b = blockIdx.x;
    int e = threadIdx.x;
    out[b * Ee + e] = embed[(size_t)input[b] * Ee + e];
}

__global__ __launch_bounds__(256) void score_doc_kernel(
    const float* __restrict__ eh, const float* __restrict__ qh,
    const float* __restrict__ bias, const float* __restrict__ v,
    float* __restrict__ score)
{
    int m = blockIdx.x;
    int t = m >> 6;
    int b = m & (Bsz - 1);
    int tid = threadIdx.x;
    const float4* e4 = (const float4*)(eh + (size_t)m * Hh);
    const float4* q4 = (const float4*)(qh + (size_t)b * Hh);
    const float4* b4 = (const float4*)bias;
    const float4* v4 = (const float4*)v;
    float4 ev = e4[tid], qv = q4[tid], bv = b4[tid], vv = v4[tid];
    float s = vv.x * tanhf(ev.x + qv.x + bv.x)
            + vv.y * tanhf(ev.y + qv.y + bv.y)
            + vv.z * tanhf(ev.z + qv.z + bv.z)
            + vv.w * tanhf(ev.w + qv.w + bv.w);
    s = block_reduce_sum(s);
    if (tid == 0) score[b * LDv + t] = s;
}

__global__ __launch_bounds__(128) void softmax_kernel(float* __restrict__ s, int T)
{
    float* x = s + (size_t)blockIdx.x * T;
    float m = -3.0e38f;
    for (int t = threadIdx.x; t < T; t += blockDim.x) m = fmaxf(m, x[t]);
    m = block_reduce_max(m);
    float sum = 0.f;
    for (int t = threadIdx.x; t < T; t += blockDim.x) sum += expf(x[t] - m);
    sum = block_reduce_sum(sum);
    float inv = 1.f / sum;
    for (int t = threadIdx.x; t < T; t += blockDim.x) x[t] = expf(x[t] - m) * inv;
}

__global__ __launch_bounds__(256) void ctx_kernel(
    const float* __restrict__ w, const float* __restrict__ enc,
    float* __restrict__ ctx, int T)
{
    __shared__ float ws[LDv];
    int b = blockIdx.y;
    int h = blockIdx.x * blockDim.x + threadIdx.x;
    for (int t = threadIdx.x; t < T; t += blockDim.x) ws[t] = w[(size_t)b * T + t];
    __syncthreads();
    float acc = 0.f;
    for (int t = 0; t < T; t++)
        acc = fmaf(ws[t], enc[((size_t)t * Bsz + b) * Hh + h], acc);
    ctx[(size_t)b * Hh + h] = acc;
}

__global__ __launch_bounds__(256) void lstm_kernel(
    const float* __restrict__ gates, const float* __restrict__ bi,
    const float* __restrict__ bh, const float* __restrict__ cprev,
    float* __restrict__ hout, float* __restrict__ cout)
{
    int idx = blockIdx.x * blockDim.x + threadIdx.x;
    if (idx >= Bsz * Hh) return;
    int b = idx >> 10;
    int j = idx & (Hh - 1);
    const float* g = gates + (size_t)b * 4 * Hh;
    float gi = g[j]          + bi[j]          + bh[j];
    float gf = g[Hh + j]     + bi[Hh + j]     + bh[Hh + j];
    float gg = g[2 * Hh + j] + bi[2 * Hh + j] + bh[2 * Hh + j];
    float go = g[3 * Hh + j] + bi[3 * Hh + j] + bh[3 * Hh + j];
    float si = 1.f / (1.f + expf(-gi));
    float sf = 1.f / (1.f + expf(-gf));
    float so = 1.f / (1.f + expf(-go));
    float c = sf * cprev[idx] + si * tanhf(gg);
    cout[idx] = c;
    hout[idx] = so * tanhf(c);
}

__global__ void concat2k(const float* __restrict__ a, int wa,
                         const float* __restrict__ b, int wb,
                         float* __restrict__ o, int rows)
{
    int W = wa + wb;
    int idx = blockIdx.x * blockDim.x + threadIdx.x;
    if (idx >= rows * W) return;
    int r = idx / W, j = idx - r * W;
    o[idx] = (j < wa) ? a[(size_t)r * wa + j] : b[(size_t)r * wb + (j - wa)];
}

__global__ __launch_bounds__(512) void logsoftmax_kernel(
    float* __restrict__ logits, const float* __restrict__ bias)
{
    float* x = logits + (size_t)blockIdx.x * Vv;
    int tid = threadIdx.x;
    float m = -3.0e38f;
    for (int v = tid; v < Vv; v += blockDim.x) m = fmaxf(m, x[v] + bias[v]);
    m = block_reduce_max(m);
    float s = 0.f;
    for (int v = tid; v < Vv; v += blockDim.x) s += expf(x[v] + bias[v] - m);
    s = block_reduce_sum(s);
    float lse = m + logf(s);
    for (int v = tid; v < Vv; v += blockDim.x) x[v] = x[v] + bias[v] - lse;
}

// ================= host =================
static inline void tcg_s(cudaStream_t st,
                         const float* A, int lda, const float* B, int ldb,
                         float* C, int ldc, int M, int N, int K, int mode,
                         const float* qadd = nullptr, const float* bias = nullptr,
                         const float* vvec = nullptr, float* score = nullptr, int T = 0)
{
    dim3 grid((N + 127) / 128, (M + 63) / 64);
    hgemm<2, 2><<<grid, 256, 0, st>>>(A, lda, B, ldb, C, ldc, M, N, K, mode,
                                      qadd, bias, vvec, score, T);
}

extern "C" void kernel_launch(void* const* d_in, const int* in_sizes, int n_in,
                              void* d_out, int out_size)
{
    const int*   input = (const int*)  d_in[0];
    const float* h0    = (const float*)d_in[1];
    const float* c0    = (const float*)d_in[2];
    const float* dh0   = (const float*)d_in[3];
    const float* dc0   = (const float*)d_in[4];
    const float* qenc  = (const float*)d_in[5];
    const float* denc  = (const float*)d_in[6];
    const float* embed = (const float*)d_in[7];
    const float* W_qa  = (const float*)d_in[8];
    const float* b_qa  = (const float*)d_in[9];
    const float* v_q   = (const float*)d_in[10];
    const float* W_da  = (const float*)d_in[11];
    const float* b_da  = (const float*)d_in[12];
    const float* v_d   = (const float*)d_in[13];
    const float* W_ih  = (const float*)d_in[14];
    const float* W_hh  = (const float*)d_in[15];
    const float* b_ih  = (const float*)d_in[16];
    const float* b_hh  = (const float*)d_in[17];
    const float* Wd_ih = (const float*)d_in[18];
    const float* Wd_hh = (const float*)d_in[19];
    const float* bd_ih = (const float*)d_in[20];
    const float* bd_hh = (const float*)d_in[21];
    const float* W_out = (const float*)d_in[22];
    const float* b_out = (const float*)d_in[23];

    float* out        = (float*)d_out;
    float* out_logits = out;
    float* out_h1     = out + (size_t)Bsz * Vv;
    float* out_c1     = out_h1 + (size_t)Bsz * Hh;
    float* out_dh     = out_c1 + (size_t)Bsz * Hh;
    float* out_dc     = out_dh + (size_t)Bsz * Hh;
    float* out_docw   = out_dc + (size_t)Bsz * Hh;

    float *p_emb, *p_qh, *p_scoreq, *p_ctxq, *p_dq, *p_dqh, *p_ehd, *p_ctxd,
          *p_gates, *p_dgates, *p_rnn;
    cudaGetSymbolAddress((void**)&p_emb,    g_embedded);
    cudaGetSymbolAddress((void**)&p_qh,     g_qh);
    cudaGetSymbolAddress((void**)&p_scoreq, g_scoreq);
    cudaGetSymbolAddress((void**)&p_ctxq,   g_ctxq);
    cudaGetSymbolAddress((void**)&p_dq,     g_dq);
    cudaGetSymbolAddress((void**)&p_dqh,    g_dqh);
    cudaGetSymbolAddress((void**)&p_ehd,    g_ehd);
    cudaGetSymbolAddress((void**)&p_ctxd,   g_ctxd);
    cudaGetSymbolAddress((void**)&p_gates,  g_gates);
    cudaGetSymbolAddress((void**)&p_dgates, g_dgates);
    cudaGetSymbolAddress((void**)&p_rnn,    g_rnn);

    __nv_bfloat16 *dencH, *dencL, *WdaH, *WdaL;
    cudaGetSymbolAddress((void**)&dencH, g_dencH);
    cudaGetSymbolAddress((void**)&dencL, g_dencL);
    cudaGetSymbolAddress((void**)&WdaH,  g_WdaH);
    cudaGetSymbolAddress((void**)&WdaL,  g_WdaL);

    static cudaStream_t s2 = nullptr, s3 = nullptr;
    static cudaEvent_t evF1, evB1, evF2, evB2, evB3;
    if (s2 == nullptr) {
        cudaStreamCreateWithFlags(&s2, cudaStreamNonBlocking);
        cudaStreamCreateWithFlags(&s3, cudaStreamNonBlocking);
        cudaEventCreateWithFlags(&evF1, cudaEventDisableTiming);
        cudaEventCreateWithFlags(&evB1, cudaEventDisableTiming);
        cudaEventCreateWithFlags(&evF2, cudaEventDisableTiming);
        cudaEventCreateWithFlags(&evB2, cudaEventDisableTiming);
        cudaEventCreateWithFlags(&evB3, cudaEventDisableTiming);
        cudaFuncSetAttribute(hgemm_bf, cudaFuncAttributeMaxDynamicSharedMemorySize, SM_BF2);
    }
    cudaStream_t s0 = 0;

    // ---- fork 1: pre-split denc/Wda then bf16 doc-energy GEMM (overlaps query chain) ----
    cudaEventRecord(evF1, s0);
    cudaStreamWaitEvent(s2, evF1, 0);
    {
        size_t totD = (size_t)(LDv * Bsz) * (Hh >> 2);
        cvt_split<<<(unsigned)((totD + 255) / 256), 256, 0, s2>>>(denc, Hh, LDv * Bsz, Hh, dencH, dencL);
        size_t totW = (size_t)Hh * (Hh >> 2);
        cvt_split<<<(unsigned)((totW + 255) / 256), 256, 0, s2>>>(W_da + 2 * Hh, 3 * Hh, Hh, Hh, WdaH, WdaL);
        dim3 grid(Hh / 128, (LDv * Bsz) / 64);
        hgemm_bf<<<grid, 256, SM_BF2, s2>>>(dencH, dencL, WdaH, WdaL,
                                            p_ehd, Hh, LDv * Bsz, Hh, Hh);
    }
    cudaEventRecord(evB1, s2);

    // ---- s0: query attention chain ----
    embed_kernel<<<Bsz, Ee, 0, s0>>>(input, embed, p_emb);
    cudaMemsetAsync(p_scoreq, 0, Bsz * LQv * sizeof(float), s0);
    tcg_s(s0, h0, Hh, W_qa, 2 * Hh, p_qh, Hh, Bsz, Hh, Hh, 0);
    tcg_s(s0, qenc, Hh, W_qa + Hh, 2 * Hh, nullptr, 0, LQv * Bsz, Hh, Hh, 2,
          p_qh, b_qa, v_q, p_scoreq, LQv);
    softmax_kernel<<<Bsz, 128, 0, s0>>>(p_scoreq, LQv);
    ctx_kernel<<<dim3(Hh / 256, Bsz), 256, 0, s0>>>(p_scoreq, qenc, p_ctxq, LQv);
    concat2k<<<(Bsz * 2 * Hh + 255) / 256, 256, 0, s0>>>(h0, Hh, p_ctxq, Hh, p_dq, Bsz);
    tcg_s(s0, p_dq, 2 * Hh, W_da, 3 * Hh, p_dqh, Hh, Bsz, Hh, 2 * Hh, 0);

    // ---- join 1 ----
    cudaStreamWaitEvent(s0, evB1, 0);
    score_doc_kernel<<<LDv * Bsz, 256, 0, s0>>>(p_ehd, p_dqh, b_da, v_d, out_docw);
    softmax_kernel<<<Bsz, 128, 0, s0>>>(out_docw, LDv);
    ctx_kernel<<<dim3(Hh / 256, Bsz), 256, 0, s0>>>(out_docw, denc, p_ctxd, LDv);

    // ---- fork 2: ctx half of output projection; fork 3: distraction LSTM ----
    cudaEventRecord(evF2, s0);
    cudaStreamWaitEvent(s2, evF2, 0);
    tcg_s(s2, p_ctxd, Hh, W_out + Hh, 2 * Hh, out_logits, Vv, Bsz, Vv, Hh, 0);
    cudaEventRecord(evB2, s2);

    cudaStreamWaitEvent(s3, evF2, 0);
    tcg_s(s3, p_ctxd, Hh, Wd_ih, Hh, p_dgates, 4 * Hh, Bsz, 4 * Hh, Hh, 0);
    tcg_s(s3, dh0,    Hh, Wd_hh, Hh, p_dgates, 4 * Hh, Bsz, 4 * Hh, Hh, 1);
    lstm_kernel<<<(Bsz * Hh + 255) / 256, 256, 0, s3>>>(p_dgates, bd_ih, bd_hh, dc0, out_dh, out_dc);
    cudaEventRecord(evB3, s3);

    // ---- s0: main LSTM chain ----
    concat2k<<<(Bsz * (Hh + Ee) + 255) / 256, 256, 0, s0>>>(p_emb, Ee, p_ctxd, Hh, p_rnn, Bsz);
    tcg_s(s0, p_rnn, Hh + Ee, W_ih, Hh + Ee, p_gates, 4 * Hh, Bsz, 4 * Hh, Hh + Ee, 0);
    tcg_s(s0, h0,    Hh,      W_hh, Hh,      p_gates, 4 * Hh, Bsz, 4 * Hh, Hh, 1);
    lstm_kernel<<<(Bsz * Hh + 255) / 256, 256, 0, s0>>>(p_gates, b_ih, b_hh, c0, out_h1, out_c1);

    // ---- join 2 ----
    cudaStreamWaitEvent(s0, evB2, 0);
    cudaStreamWaitEvent(s0, evB3, 0);
    tcg_s(s0, out_h1, Hh, W_out, 2 * Hh, out_logits, Vv, Bsz, Vv, Hh, 1);
    logsoftmax_kernel<<<Bsz, 512, 0, s0>>>(out_logits, b_out);
}